// round 6
// baseline (speedup 1.0000x reference)
#include <cuda_runtime.h>
#include <cuda_bf16.h>
#include <mma.h>
#include <cstdint>
#include <cstddef>
#include <type_traits>

using namespace nvcuda;

#define BATCH 8
#define CCH   512
#define NPIX  4096
#define CQD   64

// ---------------- static scratch (no runtime allocation) ----------------
__device__ __nv_bfloat16 g_xb[(size_t)BATCH * CCH * NPIX];
__device__ __nv_bfloat16 g_Wq[CQD * CCH];
__device__ __nv_bfloat16 g_Wk[CQD * CCH];
__device__ __nv_bfloat16 g_Wv[CCH * CCH];
__device__ __nv_bfloat16 g_q[(size_t)BATCH * CQD * NPIX];     // [b,d,i]
__device__ __nv_bfloat16 g_k[(size_t)BATCH * CQD * NPIX];     // [b,d,j]
__device__ __nv_bfloat16 g_v[(size_t)BATCH * CCH * NPIX];     // [b,c,j]
__device__ __nv_bfloat16 g_attn[(size_t)BATCH * NPIX * NPIX]; // exp(scores), unnormalized
__device__ float         g_rowsum[(size_t)BATCH * NPIX];

// ---------------- tiny utility kernels ----------------
__global__ void zero_kernel(float* p, int n) {
    int i = blockIdx.x * blockDim.x + threadIdx.x;
    if (i < n) p[i] = 0.0f;
}

__global__ void cast_kernel(const float* __restrict__ in,
                            __nv_bfloat16* __restrict__ out, size_t n4) {
    size_t i = (size_t)blockIdx.x * blockDim.x + threadIdx.x;
    if (i < n4) {
        float4 f = reinterpret_cast<const float4*>(in)[i];
        __nv_bfloat162 a = __floats2bfloat162_rn(f.x, f.y);
        __nv_bfloat162 b = __floats2bfloat162_rn(f.z, f.w);
        uint2 u;
        u.x = *reinterpret_cast<unsigned*>(&a);
        u.y = *reinterpret_cast<unsigned*>(&b);
        reinterpret_cast<uint2*>(out)[i] = u;
    }
}

// ---------------- generic bf16 wmma GEMM (round-1 proven core) ----------------
// C[M,N] = A (MxK) * B (KxN), fp32 accumulate.
// AROW: A row-major. !AROW: A col-major, A[m][k] = A[k*lda + m].
// BROW: B row-major. !BROW: B col-major, B[k][n] = B[n*ldb + k].
// EPI 1: bf16 store of (acc + bias[row])
// EPI 2: fp32 store of (gamma[0]/rowsum[col] * acc + xres[same offset])
// EPI 4: bf16 store of exp(acc); accumulate per-row sums into rowsum (atomics)
template<int BM, int BN, int BK, int WM, int WN, bool AROW, bool BROW, int EPI>
__global__ void __launch_bounds__((BM / WM) * (BN / WN) * 32)
gemm_bf16(const __nv_bfloat16* __restrict__ A, size_t strideA, int lda,
          const __nv_bfloat16* __restrict__ Bm, size_t strideB, int ldb,
          void* __restrict__ Cm, size_t strideC, int ldc,
          const float* __restrict__ bias,
          const float* __restrict__ gamma,
          const float* __restrict__ xres, size_t strideX,
          float* __restrict__ rowsum,
          int M, int N, int K)
{
    constexpr int WGM = BM / WM, WGN = BN / WN, NW = WGM * WGN;
    constexpr int MI = WM / 16, NI = WN / 16;
    constexpr int SA_R = AROW ? BM : BK, SA_C = AROW ? BK : BM;
    constexpr int SB_R = BROW ? BK : BN, SB_C = BROW ? BN : BK;

    __shared__ __nv_bfloat16 smA[SA_R][SA_C + 8];
    __shared__ __nv_bfloat16 smB[SB_R][SB_C + 8];
    __shared__ float stage[NW][16 * 16];
    __shared__ float aux[128];

    const int b = blockIdx.z;
    const __nv_bfloat16* Ab = A + strideA * (size_t)b;
    const __nv_bfloat16* Bb = Bm + strideB * (size_t)b;
    const size_t cb = strideC * (size_t)b;

    const int blockM = blockIdx.y * BM;
    const int blockN = blockIdx.x * BN;
    const int tid = threadIdx.x;
    const int wid = tid >> 5, lane = tid & 31;
    const int wm0 = (wid % WGM) * WM;
    const int wn0 = (wid / WGM) * WN;

    if (EPI == 4 && tid < BM) aux[tid] = 0.0f;

    using ALayout = typename std::conditional<AROW, wmma::row_major, wmma::col_major>::type;
    using BLayout = typename std::conditional<BROW, wmma::row_major, wmma::col_major>::type;

    wmma::fragment<wmma::accumulator, 16, 16, 16, float> acc[MI][NI];
#pragma unroll
    for (int i = 0; i < MI; i++)
#pragma unroll
        for (int j = 0; j < NI; j++) wmma::fill_fragment(acc[i][j], 0.0f);

    for (int k0 = 0; k0 < K; k0 += BK) {
        // ---- stage A tile ----
        {
            constexpr int CV = SA_C / 8;
            constexpr int IT = (SA_R * CV) / (NW * 32);
            static_assert((SA_R * CV) % (NW * 32) == 0, "A copy div");
#pragma unroll
            for (int it = 0; it < IT; ++it) {
                int idx = tid + it * NW * 32;
                int r = idx / CV, cv = idx % CV;
                const __nv_bfloat16* src = AROW
                    ? Ab + (size_t)(blockM + r) * lda + k0 + cv * 8
                    : Ab + (size_t)(k0 + r) * lda + blockM + cv * 8;
                *reinterpret_cast<uint4*>(&smA[r][cv * 8]) =
                    *reinterpret_cast<const uint4*>(src);
            }
        }
        // ---- stage B tile ----
        {
            constexpr int CV = SB_C / 8;
            constexpr int IT = (SB_R * CV) / (NW * 32);
            static_assert((SB_R * CV) % (NW * 32) == 0, "B copy div");
#pragma unroll
            for (int it = 0; it < IT; ++it) {
                int idx = tid + it * NW * 32;
                int r = idx / CV, cv = idx % CV;
                const __nv_bfloat16* src = BROW
                    ? Bb + (size_t)(k0 + r) * ldb + blockN + cv * 8
                    : Bb + (size_t)(blockN + r) * ldb + k0 + cv * 8;
                *reinterpret_cast<uint4*>(&smB[r][cv * 8]) =
                    *reinterpret_cast<const uint4*>(src);
            }
        }
        __syncthreads();

#pragma unroll
        for (int kk = 0; kk < BK; kk += 16) {
            wmma::fragment<wmma::matrix_a, 16, 16, 16, __nv_bfloat16, ALayout> af[MI];
            wmma::fragment<wmma::matrix_b, 16, 16, 16, __nv_bfloat16, BLayout> bfr[NI];
#pragma unroll
            for (int i = 0; i < MI; i++) {
                const __nv_bfloat16* p = AROW ? &smA[wm0 + i * 16][kk]
                                              : &smA[kk][wm0 + i * 16];
                wmma::load_matrix_sync(af[i], p, SA_C + 8);
            }
#pragma unroll
            for (int j = 0; j < NI; j++) {
                const __nv_bfloat16* p = BROW ? &smB[kk][wn0 + j * 16]
                                              : &smB[wn0 + j * 16][kk];
                wmma::load_matrix_sync(bfr[j], p, SB_C + 8);
            }
#pragma unroll
            for (int i = 0; i < MI; i++)
#pragma unroll
                for (int j = 0; j < NI; j++)
                    wmma::mma_sync(acc[i][j], af[i], bfr[j], acc[i][j]);
        }
        __syncthreads();
    }

    // ---- epilogue ----
    if (EPI == 2) {
        if (tid < BN) aux[tid] = gamma[0] / rowsum[(size_t)b * N + blockN + tid];
        __syncthreads();
    }

#pragma unroll
    for (int i = 0; i < MI; i++) {
#pragma unroll
        for (int j = 0; j < NI; j++) {
            wmma::store_matrix_sync(&stage[wid][0], acc[i][j], 16, wmma::mem_row_major);
            __syncwarp();
            int rowBase = blockM + wm0 + i * 16;
            int colBase = blockN + wn0 + j * 16;
#pragma unroll
            for (int e = lane; e < 256; e += 32) {
                int r = e >> 4, c = e & 15;
                float val = stage[wid][e];
                size_t o = (size_t)(rowBase + r) * ldc + colBase + c;
                if (EPI == 1) {
                    ((__nv_bfloat16*)Cm)[cb + o] = __float2bfloat16(val + bias[rowBase + r]);
                } else if (EPI == 4) {
                    float ev = __expf(val);
                    ((__nv_bfloat16*)Cm)[cb + o] = __float2bfloat16(ev);
                    atomicAdd(&aux[wm0 + i * 16 + r], ev);
                } else {  // EPI 2
                    ((float*)Cm)[cb + o] =
                        val * aux[wn0 + j * 16 + c] + xres[strideX * (size_t)b + o];
                }
            }
            __syncwarp();
        }
    }

    if (EPI == 4) {
        __syncthreads();
        if (tid < BM)
            atomicAdd(&rowsum[(size_t)b * M + blockM + tid], aux[tid]);
    }
}

// ---------------- launch ----------------
extern "C" void kernel_launch(void* const* d_in, const int* in_sizes, int n_in,
                              void* d_out, int out_size) {
    const float* x     = (const float*)d_in[0];
    const float* Wq    = (const float*)d_in[1];
    const float* bq    = (const float*)d_in[2];
    const float* Wk    = (const float*)d_in[3];
    const float* bk    = (const float*)d_in[4];
    const float* Wv    = (const float*)d_in[5];
    const float* bv    = (const float*)d_in[6];
    const float* gamma = (const float*)d_in[7];

    __nv_bfloat16 *xb, *wq, *wk, *wv, *q, *k, *v, *attn;
    float* rowsum;
    cudaGetSymbolAddress((void**)&xb, g_xb);
    cudaGetSymbolAddress((void**)&wq, g_Wq);
    cudaGetSymbolAddress((void**)&wk, g_Wk);
    cudaGetSymbolAddress((void**)&wv, g_Wv);
    cudaGetSymbolAddress((void**)&q, g_q);
    cudaGetSymbolAddress((void**)&k, g_k);
    cudaGetSymbolAddress((void**)&v, g_v);
    cudaGetSymbolAddress((void**)&attn, g_attn);
    cudaGetSymbolAddress((void**)&rowsum, g_rowsum);

    const size_t sX = (size_t)CCH * NPIX;
    const size_t sQ = (size_t)CQD * NPIX;
    const size_t sS = (size_t)NPIX * NPIX;

    // zero row sums each call (graph-replay safe)
    zero_kernel<<<(BATCH * NPIX + 255) / 256, 256>>>(rowsum, BATCH * NPIX);

    // casts
    {
        size_t n4 = (size_t)BATCH * sX / 4;
        cast_kernel<<<(unsigned)((n4 + 255) / 256), 256>>>(x, xb, n4);
        size_t nq4 = (size_t)CQD * CCH / 4;
        cast_kernel<<<(unsigned)((nq4 + 255) / 256), 256>>>(Wq, wq, nq4);
        cast_kernel<<<(unsigned)((nq4 + 255) / 256), 256>>>(Wk, wk, nq4);
        size_t nv4 = (size_t)CCH * CCH / 4;
        cast_kernel<<<(unsigned)((nv4 + 255) / 256), 256>>>(Wv, wv, nv4);
    }

    // q = Wq @ xb + bq ; k = Wk @ xb + bk   [64 x 4096] per batch, bf16 out
    {
        dim3 g(NPIX / 128, CQD / 64, BATCH);
        gemm_bf16<64, 128, 64, 32, 32, true, true, 1><<<g, 256>>>(
            wq, 0, CCH, xb, sX, NPIX, q, sQ, NPIX, bq, nullptr, nullptr, 0,
            nullptr, CQD, NPIX, CCH);
        gemm_bf16<64, 128, 64, 32, 32, true, true, 1><<<g, 256>>>(
            wk, 0, CCH, xb, sX, NPIX, k, sQ, NPIX, bk, nullptr, nullptr, 0,
            nullptr, CQD, NPIX, CCH);
    }

    // v = Wv @ xb + bv   [512 x 4096] per batch, bf16 out
    {
        dim3 g(NPIX / 128, CCH / 128, BATCH);
        gemm_bf16<128, 128, 64, 64, 32, true, true, 1><<<g, 256>>>(
            wv, 0, CCH, xb, sX, NPIX, v, sX, NPIX, bv, nullptr, nullptr, 0,
            nullptr, CCH, NPIX, CCH);
    }

    // attn[i,j] = exp(sum_d q[d,i]*k[d,j])  bf16, + rowsum accumulation
    {
        dim3 g(NPIX / 128, NPIX / 128, BATCH);
        gemm_bf16<128, 128, 64, 64, 32, false, true, 4><<<g, 256>>>(
            q, sQ, NPIX, k, sQ, NPIX, attn, sS, NPIX, nullptr, nullptr,
            nullptr, 0, rowsum, NPIX, NPIX, CQD);
    }

    // out[c,i] = gamma/rowsum[i] * sum_j v[c,j]*attn[i,j] + x[c,i]  -> fp32
    {
        dim3 g(NPIX / 128, CCH / 128, BATCH);
        gemm_bf16<128, 128, 64, 64, 32, true, false, 2><<<g, 256>>>(
            v, sX, NPIX, attn, sS, NPIX, d_out, sX, NPIX, nullptr, gamma,
            x, sX, rowsum, CCH, NPIX, NPIX);
    }
}

// round 8
// speedup vs baseline: 4.1166x; 4.1166x over previous

#include <cuda_runtime.h>
#include <cuda_bf16.h>
#include <mma.h>
#include <cstdint>
#include <cstddef>
#include <type_traits>

using namespace nvcuda;

#define BATCH 8
#define CCH   512
#define NPIX  4096
#define CQD   64

// ---------------- static scratch (no runtime allocation allowed) ----------------
__device__ __nv_bfloat16 g_xb[(size_t)BATCH * CCH * NPIX];     // x in bf16
__device__ __nv_bfloat16 g_Wq[CQD * CCH];
__device__ __nv_bfloat16 g_Wk[CQD * CCH];
__device__ __nv_bfloat16 g_Wv[CCH * CCH];
__device__ __nv_bfloat16 g_q[(size_t)BATCH * CQD * NPIX];
__device__ __nv_bfloat16 g_k[(size_t)BATCH * CQD * NPIX];
__device__ __nv_bfloat16 g_v[(size_t)BATCH * CCH * NPIX];
__device__ float         g_scores[(size_t)BATCH * NPIX * NPIX]; // 536 MB
__device__ __nv_bfloat16 g_attn[(size_t)BATCH * NPIX * NPIX];   // 268 MB

// ---------------- fp32 -> bf16 cast (vectorized) ----------------
__global__ void cast_kernel(const float* __restrict__ in,
                            __nv_bfloat16* __restrict__ out, size_t n4) {
    size_t i = (size_t)blockIdx.x * blockDim.x + threadIdx.x;
    if (i < n4) {
        float4 f = reinterpret_cast<const float4*>(in)[i];
        __nv_bfloat162 a = __floats2bfloat162_rn(f.x, f.y);
        __nv_bfloat162 b = __floats2bfloat162_rn(f.z, f.w);
        uint2 u;
        u.x = *reinterpret_cast<unsigned*>(&a);
        u.y = *reinterpret_cast<unsigned*>(&b);
        reinterpret_cast<uint2*>(out)[i] = u;
    }
}

// ---------------- generic bf16 wmma GEMM ----------------
// C[M,N] = A (MxK) * B (KxN), fp32 accumulate.
// AROW: A row-major (lda=K-stride). !AROW: A col-major, A[m][k] = A[k*lda + m].
// BROW: B row-major. !BROW: B col-major, B[k][n] = B[n*ldb + k].
// EPI 0: fp32 plain store
// EPI 1: bf16 store of (acc + bias[row])
// EPI 2: fp32 store of (gamma[0]*acc + xres[same offset])
template<int BM, int BN, int BK, int WM, int WN, bool AROW, bool BROW, int EPI>
__global__ void __launch_bounds__((BM / WM) * (BN / WN) * 32)
gemm_bf16(const __nv_bfloat16* __restrict__ A, size_t strideA, int lda,
          const __nv_bfloat16* __restrict__ Bm, size_t strideB, int ldb,
          void* __restrict__ Cm, size_t strideC, int ldc,
          const float* __restrict__ bias,
          const float* __restrict__ gamma,
          const float* __restrict__ xres, size_t strideX,
          int M, int N, int K)
{
    constexpr int WGM = BM / WM, WGN = BN / WN, NW = WGM * WGN;
    constexpr int MI = WM / 16, NI = WN / 16;
    constexpr int SA_R = AROW ? BM : BK, SA_C = AROW ? BK : BM;
    constexpr int SB_R = BROW ? BK : BN, SB_C = BROW ? BN : BK;

    __shared__ __nv_bfloat16 smA[SA_R][SA_C + 8];
    __shared__ __nv_bfloat16 smB[SB_R][SB_C + 8];
    __shared__ float stage[NW][16 * 16];

    const int b = blockIdx.z;
    const __nv_bfloat16* Ab = A + strideA * (size_t)b;
    const __nv_bfloat16* Bb = Bm + strideB * (size_t)b;
    const size_t cb = strideC * (size_t)b;

    const int blockM = blockIdx.y * BM;
    const int blockN = blockIdx.x * BN;
    const int tid = threadIdx.x;
    const int wid = tid >> 5, lane = tid & 31;
    const int wm0 = (wid % WGM) * WM;
    const int wn0 = (wid / WGM) * WN;

    using ALayout = typename std::conditional<AROW, wmma::row_major, wmma::col_major>::type;
    using BLayout = typename std::conditional<BROW, wmma::row_major, wmma::col_major>::type;

    wmma::fragment<wmma::accumulator, 16, 16, 16, float> acc[MI][NI];
#pragma unroll
    for (int i = 0; i < MI; i++)
#pragma unroll
        for (int j = 0; j < NI; j++) wmma::fill_fragment(acc[i][j], 0.0f);

    for (int k0 = 0; k0 < K; k0 += BK) {
        // ---- stage A tile ----
        {
            constexpr int CV = SA_C / 8;
            constexpr int IT = (SA_R * CV) / (NW * 32);
            static_assert((SA_R * CV) % (NW * 32) == 0, "A copy div");
#pragma unroll
            for (int it = 0; it < IT; ++it) {
                int idx = tid + it * NW * 32;
                int r = idx / CV, cv = idx % CV;
                const __nv_bfloat16* src = AROW
                    ? Ab + (size_t)(blockM + r) * lda + k0 + cv * 8
                    : Ab + (size_t)(k0 + r) * lda + blockM + cv * 8;
                *reinterpret_cast<uint4*>(&smA[r][cv * 8]) =
                    *reinterpret_cast<const uint4*>(src);
            }
        }
        // ---- stage B tile ----
        {
            constexpr int CV = SB_C / 8;
            constexpr int IT = (SB_R * CV) / (NW * 32);
            static_assert((SB_R * CV) % (NW * 32) == 0, "B copy div");
#pragma unroll
            for (int it = 0; it < IT; ++it) {
                int idx = tid + it * NW * 32;
                int r = idx / CV, cv = idx % CV;
                const __nv_bfloat16* src = BROW
                    ? Bb + (size_t)(k0 + r) * ldb + blockN + cv * 8
                    : Bb + (size_t)(blockN + r) * ldb + k0 + cv * 8;
                *reinterpret_cast<uint4*>(&smB[r][cv * 8]) =
                    *reinterpret_cast<const uint4*>(src);
            }
        }
        __syncthreads();

#pragma unroll
        for (int kk = 0; kk < BK; kk += 16) {
            wmma::fragment<wmma::matrix_a, 16, 16, 16, __nv_bfloat16, ALayout> af[MI];
            wmma::fragment<wmma::matrix_b, 16, 16, 16, __nv_bfloat16, BLayout> bfr[NI];
#pragma unroll
            for (int i = 0; i < MI; i++) {
                const __nv_bfloat16* p = AROW ? &smA[wm0 + i * 16][kk]
                                              : &smA[kk][wm0 + i * 16];
                wmma::load_matrix_sync(af[i], p, SA_C + 8);
            }
#pragma unroll
            for (int j = 0; j < NI; j++) {
                const __nv_bfloat16* p = BROW ? &smB[kk][wn0 + j * 16]
                                              : &smB[wn0 + j * 16][kk];
                wmma::load_matrix_sync(bfr[j], p, SB_C + 8);
            }
#pragma unroll
            for (int i = 0; i < MI; i++)
#pragma unroll
                for (int j = 0; j < NI; j++)
                    wmma::mma_sync(acc[i][j], af[i], bfr[j], acc[i][j]);
        }
        __syncthreads();
    }

    // ---- epilogue via per-warp staging ----
    float gval = 0.0f;
    if (EPI == 2) gval = gamma[0];

#pragma unroll
    for (int i = 0; i < MI; i++) {
#pragma unroll
        for (int j = 0; j < NI; j++) {
            wmma::store_matrix_sync(&stage[wid][0], acc[i][j], 16, wmma::mem_row_major);
            __syncwarp();
            int rowBase = blockM + wm0 + i * 16;
            int colBase = blockN + wn0 + j * 16;
#pragma unroll
            for (int e = lane; e < 256; e += 32) {
                int r = e >> 4, c = e & 15;
                float val = stage[wid][e];
                size_t o = (size_t)(rowBase + r) * ldc + colBase + c;
                if (EPI == 0) {
                    ((float*)Cm)[cb + o] = val;
                } else if (EPI == 1) {
                    ((__nv_bfloat16*)Cm)[cb + o] = __float2bfloat16(val + bias[rowBase + r]);
                } else {
                    ((float*)Cm)[cb + o] = gval * val + xres[strideX * (size_t)b + o];
                }
            }
            __syncwarp();
        }
    }
}

// ---------------- row softmax: fp32 scores -> bf16 probs ----------------
__global__ void softmax_kernel(const float* __restrict__ s,
                               __nv_bfloat16* __restrict__ p) {
    size_t row = blockIdx.x;  // b*NPIX + i
    const float4* src = reinterpret_cast<const float4*>(s + row * NPIX);
    uint2* dst = reinterpret_cast<uint2*>(p + row * NPIX);
    int t = threadIdx.x;

    float4 v[4];
    float mx = -1e30f;
#pragma unroll
    for (int i = 0; i < 4; i++) {
        v[i] = src[i * 256 + t];
        mx = fmaxf(mx, fmaxf(fmaxf(v[i].x, v[i].y), fmaxf(v[i].z, v[i].w)));
    }
    __shared__ float red[8];
#pragma unroll
    for (int o = 16; o > 0; o >>= 1) mx = fmaxf(mx, __shfl_xor_sync(0xffffffffu, mx, o));
    if ((t & 31) == 0) red[t >> 5] = mx;
    __syncthreads();
    float bmax = red[0];
#pragma unroll
    for (int w = 1; w < 8; w++) bmax = fmaxf(bmax, red[w]);
    __syncthreads();

    float e[16];
    float sum = 0.0f;
#pragma unroll
    for (int i = 0; i < 4; i++) {
        e[i * 4 + 0] = __expf(v[i].x - bmax);
        e[i * 4 + 1] = __expf(v[i].y - bmax);
        e[i * 4 + 2] = __expf(v[i].z - bmax);
        e[i * 4 + 3] = __expf(v[i].w - bmax);
        sum += e[i * 4 + 0] + e[i * 4 + 1] + e[i * 4 + 2] + e[i * 4 + 3];
    }
#pragma unroll
    for (int o = 16; o > 0; o >>= 1) sum += __shfl_xor_sync(0xffffffffu, sum, o);
    if ((t & 31) == 0) red[t >> 5] = sum;
    __syncthreads();
    float tot = 0.0f;
#pragma unroll
    for (int w = 0; w < 8; w++) tot += red[w];
    float inv = 1.0f / tot;

#pragma unroll
    for (int i = 0; i < 4; i++) {
        __nv_bfloat162 h0 = __floats2bfloat162_rn(e[i * 4 + 0] * inv, e[i * 4 + 1] * inv);
        __nv_bfloat162 h1 = __floats2bfloat162_rn(e[i * 4 + 2] * inv, e[i * 4 + 3] * inv);
        uint2 u;
        u.x = *reinterpret_cast<unsigned*>(&h0);
        u.y = *reinterpret_cast<unsigned*>(&h1);
        dst[i * 256 + t] = u;
    }
}

// ---------------- launch ----------------
extern "C" void kernel_launch(void* const* d_in, const int* in_sizes, int n_in,
                              void* d_out, int out_size) {
    const float* x     = (const float*)d_in[0];
    const float* Wq    = (const float*)d_in[1];
    const float* bq    = (const float*)d_in[2];
    const float* Wk    = (const float*)d_in[3];
    const float* bk    = (const float*)d_in[4];
    const float* Wv    = (const float*)d_in[5];
    const float* bv    = (const float*)d_in[6];
    const float* gamma = (const float*)d_in[7];

    __nv_bfloat16 *xb, *wq, *wk, *wv, *q, *k, *v, *attn;
    float* scores;
    cudaGetSymbolAddress((void**)&xb, g_xb);
    cudaGetSymbolAddress((void**)&wq, g_Wq);
    cudaGetSymbolAddress((void**)&wk, g_Wk);
    cudaGetSymbolAddress((void**)&wv, g_Wv);
    cudaGetSymbolAddress((void**)&q, g_q);
    cudaGetSymbolAddress((void**)&k, g_k);
    cudaGetSymbolAddress((void**)&v, g_v);
    cudaGetSymbolAddress((void**)&scores, g_scores);
    cudaGetSymbolAddress((void**)&attn, g_attn);

    const size_t sX = (size_t)CCH * NPIX;   // per-batch x/v/out stride
    const size_t sQ = (size_t)CQD * NPIX;   // per-batch q/k stride
    const size_t sS = (size_t)NPIX * NPIX;  // per-batch scores/attn stride

    // casts
    {
        size_t n4 = (size_t)BATCH * sX / 4;
        cast_kernel<<<(unsigned)((n4 + 255) / 256), 256>>>(x, xb, n4);
        size_t nq4 = (size_t)CQD * CCH / 4;
        cast_kernel<<<(unsigned)((nq4 + 255) / 256), 256>>>(Wq, wq, nq4);
        cast_kernel<<<(unsigned)((nq4 + 255) / 256), 256>>>(Wk, wk, nq4);
        size_t nv4 = (size_t)CCH * CCH / 4;
        cast_kernel<<<(unsigned)((nv4 + 255) / 256), 256>>>(Wv, wv, nv4);
    }

    // q = Wq @ xb + bq   [64 x 4096] per batch, bf16 out
    {
        dim3 g(NPIX / 128, CQD / 64, BATCH);
        gemm_bf16<64, 128, 64, 32, 32, true, true, 1><<<g, 256>>>(
            wq, 0, CCH, xb, sX, NPIX, q, sQ, NPIX, bq, nullptr, nullptr, 0,
            CQD, NPIX, CCH);
        gemm_bf16<64, 128, 64, 32, 32, true, true, 1><<<g, 256>>>(
            wk, 0, CCH, xb, sX, NPIX, k, sQ, NPIX, bk, nullptr, nullptr, 0,
            CQD, NPIX, CCH);
    }

    // v = Wv @ xb + bv   [512 x 4096] per batch, bf16 out
    {
        dim3 g(NPIX / 128, CCH / 128, BATCH);
        gemm_bf16<128, 128, 64, 64, 32, true, true, 1><<<g, 256>>>(
            wv, 0, CCH, xb, sX, NPIX, v, sX, NPIX, bv, nullptr, nullptr, 0,
            CCH, NPIX, CCH);
    }

    // scores[i,j] = sum_d q[d,i]*k[d,j]  -> fp32 [4096 x 4096] per batch
    {
        dim3 g(NPIX / 128, NPIX / 128, BATCH);
        gemm_bf16<128, 128, 64, 64, 32, false, true, 0><<<g, 256>>>(
            q, sQ, NPIX, k, sQ, NPIX, scores, sS, NPIX, nullptr, nullptr,
            nullptr, 0, NPIX, NPIX, CQD);
    }

    // softmax rows -> bf16 attn
    softmax_kernel<<<BATCH * NPIX, 256>>>(scores, attn);

    // out[c,i] = gamma * sum_j v[c,j]*attn[i,j] + x[c,i]  -> d_out fp32
    {
        dim3 g(NPIX / 128, CCH / 128, BATCH);
        gemm_bf16<128, 128, 64, 64, 32, true, false, 2><<<g, 256>>>(
            v, sX, NPIX, attn, sS, NPIX, d_out, sX, NPIX, nullptr, gamma,
            x, sX, CCH, NPIX, NPIX);
    }
}

// round 9
// speedup vs baseline: 4.3020x; 1.0450x over previous

#include <cuda_runtime.h>
#include <cuda_bf16.h>
#include <mma.h>
#include <cstdint>
#include <cstddef>
#include <type_traits>

using namespace nvcuda;

#define BATCH 8
#define CCH   512
#define NPIX  4096
#define CQD   64

// ---------------- static scratch (no runtime allocation allowed) ----------------
__device__ __nv_bfloat16 g_xb[(size_t)BATCH * CCH * NPIX];     // x in bf16
__device__ __nv_bfloat16 g_Wq[CQD * CCH];
__device__ __nv_bfloat16 g_Wk[CQD * CCH];
__device__ __nv_bfloat16 g_Wv[CCH * CCH];
__device__ __nv_bfloat16 g_q[(size_t)BATCH * CQD * NPIX];
__device__ __nv_bfloat16 g_k[(size_t)BATCH * CQD * NPIX];
__device__ __nv_bfloat16 g_v[(size_t)BATCH * CCH * NPIX];
__device__ __nv_bfloat16 g_attn[(size_t)BATCH * NPIX * NPIX];  // exp(scores), unnormalized
__device__ float         g_rowsum[(size_t)BATCH * NPIX];

// ---------------- fp32 -> bf16 cast (vectorized) ----------------
__global__ void cast_kernel(const float* __restrict__ in,
                            __nv_bfloat16* __restrict__ out, size_t n4) {
    size_t i = (size_t)blockIdx.x * blockDim.x + threadIdx.x;
    if (i < n4) {
        float4 f = reinterpret_cast<const float4*>(in)[i];
        __nv_bfloat162 a = __floats2bfloat162_rn(f.x, f.y);
        __nv_bfloat162 b = __floats2bfloat162_rn(f.z, f.w);
        uint2 u;
        u.x = *reinterpret_cast<unsigned*>(&a);
        u.y = *reinterpret_cast<unsigned*>(&b);
        reinterpret_cast<uint2*>(out)[i] = u;
    }
}

// ---------------- rowsum reduction over attn rows ----------------
// one block (128 threads) per row; row length NPIX bf16
__global__ void rowsum_kernel(const __nv_bfloat16* __restrict__ attn,
                              float* __restrict__ rowsum) {
    size_t row = blockIdx.x;
    const uint2* src = reinterpret_cast<const uint2*>(attn + row * NPIX);
    int t = threadIdx.x;
    float s = 0.0f;
#pragma unroll
    for (int i = 0; i < 8; ++i) {
        uint2 u = src[t + 128 * i];
        __nv_bfloat162 h0 = *reinterpret_cast<__nv_bfloat162*>(&u.x);
        __nv_bfloat162 h1 = *reinterpret_cast<__nv_bfloat162*>(&u.y);
        s += __bfloat162float(__low2bfloat16(h0)) + __bfloat162float(__high2bfloat16(h0));
        s += __bfloat162float(__low2bfloat16(h1)) + __bfloat162float(__high2bfloat16(h1));
    }
#pragma unroll
    for (int o = 16; o > 0; o >>= 1) s += __shfl_xor_sync(0xffffffffu, s, o);
    __shared__ float red[4];
    if ((t & 31) == 0) red[t >> 5] = s;
    __syncthreads();
    if (t == 0) rowsum[row] = red[0] + red[1] + red[2] + red[3];
}

// ---------------- generic bf16 wmma GEMM (round-1 proven core) ----------------
// C[M,N] = A (MxK) * B (KxN), fp32 accumulate.
// AROW: A row-major (lda=K-stride). !AROW: A col-major, A[m][k] = A[k*lda + m].
// BROW: B row-major. !BROW: B col-major, B[k][n] = B[n*ldb + k].
// EPI 1: bf16 store of (acc + bias[row])
// EPI 2: fp32 store of (gamma[0]/rowsum[col] * acc + xres[same offset])
// EPI 4: bf16 store of exp(acc)   (pure store, no atomics)
template<int BM, int BN, int BK, int WM, int WN, bool AROW, bool BROW, int EPI>
__global__ void __launch_bounds__((BM / WM) * (BN / WN) * 32)
gemm_bf16(const __nv_bfloat16* __restrict__ A, size_t strideA, int lda,
          const __nv_bfloat16* __restrict__ Bm, size_t strideB, int ldb,
          void* __restrict__ Cm, size_t strideC, int ldc,
          const float* __restrict__ bias,
          const float* __restrict__ gamma,
          const float* __restrict__ xres, size_t strideX,
          const float* __restrict__ rowsum,
          int M, int N, int K)
{
    constexpr int WGM = BM / WM, WGN = BN / WN, NW = WGM * WGN;
    constexpr int MI = WM / 16, NI = WN / 16;
    constexpr int SA_R = AROW ? BM : BK, SA_C = AROW ? BK : BM;
    constexpr int SB_R = BROW ? BK : BN, SB_C = BROW ? BN : BK;

    __shared__ __nv_bfloat16 smA[SA_R][SA_C + 8];
    __shared__ __nv_bfloat16 smB[SB_R][SB_C + 8];
    __shared__ float stage[NW][16 * 16];
    __shared__ float aux[128];

    const int b = blockIdx.z;
    const __nv_bfloat16* Ab = A + strideA * (size_t)b;
    const __nv_bfloat16* Bb = Bm + strideB * (size_t)b;
    const size_t cb = strideC * (size_t)b;

    const int blockM = blockIdx.y * BM;
    const int blockN = blockIdx.x * BN;
    const int tid = threadIdx.x;
    const int wid = tid >> 5, lane = tid & 31;
    const int wm0 = (wid % WGM) * WM;
    const int wn0 = (wid / WGM) * WN;

    using ALayout = typename std::conditional<AROW, wmma::row_major, wmma::col_major>::type;
    using BLayout = typename std::conditional<BROW, wmma::row_major, wmma::col_major>::type;

    wmma::fragment<wmma::accumulator, 16, 16, 16, float> acc[MI][NI];
#pragma unroll
    for (int i = 0; i < MI; i++)
#pragma unroll
        for (int j = 0; j < NI; j++) wmma::fill_fragment(acc[i][j], 0.0f);

    for (int k0 = 0; k0 < K; k0 += BK) {
        // ---- stage A tile ----
        {
            constexpr int CV = SA_C / 8;
            constexpr int IT = (SA_R * CV) / (NW * 32);
            static_assert((SA_R * CV) % (NW * 32) == 0, "A copy div");
#pragma unroll
            for (int it = 0; it < IT; ++it) {
                int idx = tid + it * NW * 32;
                int r = idx / CV, cv = idx % CV;
                const __nv_bfloat16* src = AROW
                    ? Ab + (size_t)(blockM + r) * lda + k0 + cv * 8
                    : Ab + (size_t)(k0 + r) * lda + blockM + cv * 8;
                *reinterpret_cast<uint4*>(&smA[r][cv * 8]) =
                    *reinterpret_cast<const uint4*>(src);
            }
        }
        // ---- stage B tile ----
        {
            constexpr int CV = SB_C / 8;
            constexpr int IT = (SB_R * CV) / (NW * 32);
            static_assert((SB_R * CV) % (NW * 32) == 0, "B copy div");
#pragma unroll
            for (int it = 0; it < IT; ++it) {
                int idx = tid + it * NW * 32;
                int r = idx / CV, cv = idx % CV;
                const __nv_bfloat16* src = BROW
                    ? Bb + (size_t)(k0 + r) * ldb + blockN + cv * 8
                    : Bb + (size_t)(blockN + r) * ldb + k0 + cv * 8;
                *reinterpret_cast<uint4*>(&smB[r][cv * 8]) =
                    *reinterpret_cast<const uint4*>(src);
            }
        }
        __syncthreads();

#pragma unroll
        for (int kk = 0; kk < BK; kk += 16) {
            wmma::fragment<wmma::matrix_a, 16, 16, 16, __nv_bfloat16, ALayout> af[MI];
            wmma::fragment<wmma::matrix_b, 16, 16, 16, __nv_bfloat16, BLayout> bfr[NI];
#pragma unroll
            for (int i = 0; i < MI; i++) {
                const __nv_bfloat16* p = AROW ? &smA[wm0 + i * 16][kk]
                                              : &smA[kk][wm0 + i * 16];
                wmma::load_matrix_sync(af[i], p, SA_C + 8);
            }
#pragma unroll
            for (int j = 0; j < NI; j++) {
                const __nv_bfloat16* p = BROW ? &smB[kk][wn0 + j * 16]
                                              : &smB[wn0 + j * 16][kk];
                wmma::load_matrix_sync(bfr[j], p, SB_C + 8);
            }
#pragma unroll
            for (int i = 0; i < MI; i++)
#pragma unroll
                for (int j = 0; j < NI; j++)
                    wmma::mma_sync(acc[i][j], af[i], bfr[j], acc[i][j]);
        }
        __syncthreads();
    }

    // ---- epilogue via per-warp staging ----
    if (EPI == 2) {
        if (tid < BN) aux[tid] = gamma[0] / rowsum[(size_t)b * N + blockN + tid];
        __syncthreads();
    }

#pragma unroll
    for (int i = 0; i < MI; i++) {
#pragma unroll
        for (int j = 0; j < NI; j++) {
            wmma::store_matrix_sync(&stage[wid][0], acc[i][j], 16, wmma::mem_row_major);
            __syncwarp();
            int rowBase = blockM + wm0 + i * 16;
            int colBase = blockN + wn0 + j * 16;
#pragma unroll
            for (int e = lane; e < 256; e += 32) {
                int r = e >> 4, c = e & 15;
                float val = stage[wid][e];
                size_t o = (size_t)(rowBase + r) * ldc + colBase + c;
                if (EPI == 1) {
                    ((__nv_bfloat16*)Cm)[cb + o] = __float2bfloat16(val + bias[rowBase + r]);
                } else if (EPI == 4) {
                    ((__nv_bfloat16*)Cm)[cb + o] = __float2bfloat16(__expf(val));
                } else {  // EPI 2
                    ((float*)Cm)[cb + o] =
                        val * aux[wn0 + j * 16 + c] + xres[strideX * (size_t)b + o];
                }
            }
            __syncwarp();
        }
    }
}

// ---------------- launch ----------------
extern "C" void kernel_launch(void* const* d_in, const int* in_sizes, int n_in,
                              void* d_out, int out_size) {
    const float* x     = (const float*)d_in[0];
    const float* Wq    = (const float*)d_in[1];
    const float* bq    = (const float*)d_in[2];
    const float* Wk    = (const float*)d_in[3];
    const float* bk    = (const float*)d_in[4];
    const float* Wv    = (const float*)d_in[5];
    const float* bv    = (const float*)d_in[6];
    const float* gamma = (const float*)d_in[7];

    __nv_bfloat16 *xb, *wq, *wk, *wv, *q, *k, *v, *attn;
    float* rowsum;
    cudaGetSymbolAddress((void**)&xb, g_xb);
    cudaGetSymbolAddress((void**)&wq, g_Wq);
    cudaGetSymbolAddress((void**)&wk, g_Wk);
    cudaGetSymbolAddress((void**)&wv, g_Wv);
    cudaGetSymbolAddress((void**)&q, g_q);
    cudaGetSymbolAddress((void**)&k, g_k);
    cudaGetSymbolAddress((void**)&v, g_v);
    cudaGetSymbolAddress((void**)&attn, g_attn);
    cudaGetSymbolAddress((void**)&rowsum, g_rowsum);

    const size_t sX = (size_t)CCH * NPIX;   // per-batch x/v/out stride
    const size_t sQ = (size_t)CQD * NPIX;   // per-batch q/k stride
    const size_t sS = (size_t)NPIX * NPIX;  // per-batch attn stride

    // casts
    {
        size_t n4 = (size_t)BATCH * sX / 4;
        cast_kernel<<<(unsigned)((n4 + 255) / 256), 256>>>(x, xb, n4);
        size_t nq4 = (size_t)CQD * CCH / 4;
        cast_kernel<<<(unsigned)((nq4 + 255) / 256), 256>>>(Wq, wq, nq4);
        cast_kernel<<<(unsigned)((nq4 + 255) / 256), 256>>>(Wk, wk, nq4);
        size_t nv4 = (size_t)CCH * CCH / 4;
        cast_kernel<<<(unsigned)((nv4 + 255) / 256), 256>>>(Wv, wv, nv4);
    }

    // q = Wq @ xb + bq   [64 x 4096] per batch, bf16 out
    {
        dim3 g(NPIX / 128, CQD / 64, BATCH);
        gemm_bf16<64, 128, 64, 32, 32, true, true, 1><<<g, 256>>>(
            wq, 0, CCH, xb, sX, NPIX, q, sQ, NPIX, bq, nullptr, nullptr, 0,
            nullptr, CQD, NPIX, CCH);
        gemm_bf16<64, 128, 64, 32, 32, true, true, 1><<<g, 256>>>(
            wk, 0, CCH, xb, sX, NPIX, k, sQ, NPIX, bk, nullptr, nullptr, 0,
            nullptr, CQD, NPIX, CCH);
    }

    // v = Wv @ xb + bv   [512 x 4096] per batch, bf16 out
    {
        dim3 g(NPIX / 128, CCH / 128, BATCH);
        gemm_bf16<128, 128, 64, 64, 32, true, true, 1><<<g, 256>>>(
            wv, 0, CCH, xb, sX, NPIX, v, sX, NPIX, bv, nullptr, nullptr, 0,
            nullptr, CCH, NPIX, CCH);
    }

    // attn[i,j] = exp(sum_d q[d,i]*k[d,j])  bf16, unnormalized
    {
        dim3 g(NPIX / 128, NPIX / 128, BATCH);
        gemm_bf16<128, 128, 64, 64, 32, false, true, 4><<<g, 256>>>(
            q, sQ, NPIX, k, sQ, NPIX, attn, sS, NPIX, nullptr, nullptr,
            nullptr, 0, nullptr, NPIX, NPIX, CQD);
    }

    // rowsum[b,i] = sum_j attn[b,i,j]
    rowsum_kernel<<<BATCH * NPIX, 128>>>(attn, rowsum);

    // out[c,i] = gamma/rowsum[i] * sum_j v[c,j]*attn[i,j] + x[c,i]  -> fp32
    {
        dim3 g(NPIX / 128, CCH / 128, BATCH);
        gemm_bf16<128, 128, 64, 64, 32, true, false, 2><<<g, 256>>>(
            v, sX, NPIX, attn, sS, NPIX, d_out, sX, NPIX, nullptr, gamma,
            x, sX, rowsum, CCH, NPIX, NPIX);
    }
}

// round 10
// speedup vs baseline: 5.1728x; 1.2024x over previous

#include <cuda_runtime.h>
#include <cuda_bf16.h>
#include <mma.h>
#include <cstdint>
#include <cstddef>
#include <type_traits>

using namespace nvcuda;

#define BATCH 8
#define CCH   512
#define NPIX  4096
#define CQD   64

// ---------------- static scratch (no runtime allocation allowed) ----------------
__device__ __nv_bfloat16 g_xb[(size_t)BATCH * CCH * NPIX];     // x in bf16
__device__ __nv_bfloat16 g_Wq[CQD * CCH];
__device__ __nv_bfloat16 g_Wk[CQD * CCH];
__device__ __nv_bfloat16 g_Wv[CCH * CCH];
__device__ __nv_bfloat16 g_q[(size_t)BATCH * CQD * NPIX];
__device__ __nv_bfloat16 g_k[(size_t)BATCH * CQD * NPIX];
__device__ __nv_bfloat16 g_v[(size_t)BATCH * CCH * NPIX];
__device__ __nv_bfloat16 g_attn[(size_t)BATCH * NPIX * NPIX];  // exp(scores), unnormalized
__device__ float         g_rowsum[(size_t)BATCH * NPIX];

// ---------------- fp32 -> bf16 cast (vectorized) ----------------
__global__ void cast_kernel(const float* __restrict__ in,
                            __nv_bfloat16* __restrict__ out, size_t n4) {
    size_t i = (size_t)blockIdx.x * blockDim.x + threadIdx.x;
    if (i < n4) {
        float4 f = reinterpret_cast<const float4*>(in)[i];
        __nv_bfloat162 a = __floats2bfloat162_rn(f.x, f.y);
        __nv_bfloat162 b = __floats2bfloat162_rn(f.z, f.w);
        uint2 u;
        u.x = *reinterpret_cast<unsigned*>(&a);
        u.y = *reinterpret_cast<unsigned*>(&b);
        reinterpret_cast<uint2*>(out)[i] = u;
    }
}

// ---------------- rowsum reduction over attn rows ----------------
__global__ void rowsum_kernel(const __nv_bfloat16* __restrict__ attn,
                              float* __restrict__ rowsum) {
    size_t row = blockIdx.x;
    const uint2* src = reinterpret_cast<const uint2*>(attn + row * NPIX);
    int t = threadIdx.x;
    float s = 0.0f;
#pragma unroll
    for (int i = 0; i < 8; ++i) {
        uint2 u = src[t + 128 * i];
        __nv_bfloat162 h0 = *reinterpret_cast<__nv_bfloat162*>(&u.x);
        __nv_bfloat162 h1 = *reinterpret_cast<__nv_bfloat162*>(&u.y);
        s += __bfloat162float(__low2bfloat16(h0)) + __bfloat162float(__high2bfloat16(h0));
        s += __bfloat162float(__low2bfloat16(h1)) + __bfloat162float(__high2bfloat16(h1));
    }
#pragma unroll
    for (int o = 16; o > 0; o >>= 1) s += __shfl_xor_sync(0xffffffffu, s, o);
    __shared__ float red[4];
    if ((t & 31) == 0) red[t >> 5] = s;
    __syncthreads();
    if (t == 0) rowsum[row] = red[0] + red[1] + red[2] + red[3];
}

// ---------------- bf16 wmma GEMM with register-prefetch pipelining ----------------
// C[M,N] = A (MxK) * B (KxN), fp32 accumulate.
// AROW: A row-major. !AROW: A col-major, A[m][k] = A[k*lda + m].
// BROW: B row-major. !BROW: B col-major, B[k][n] = B[n*ldb + k].
// EPI 1: bf16 store of (acc + bias[row])
// EPI 2: fp32 store of (gamma[0]/rowsum[col] * acc + xres[same offset])
// EPI 4: bf16 store of exp(acc)
template<int BM, int BN, int BK, int WM, int WN, bool AROW, bool BROW, int EPI>
__global__ void __launch_bounds__((BM / WM) * (BN / WN) * 32)
gemm_bf16(const __nv_bfloat16* __restrict__ A, size_t strideA, int lda,
          const __nv_bfloat16* __restrict__ Bm, size_t strideB, int ldb,
          void* __restrict__ Cm, size_t strideC, int ldc,
          const float* __restrict__ bias,
          const float* __restrict__ gamma,
          const float* __restrict__ xres, size_t strideX,
          const float* __restrict__ rowsum,
          int M, int N, int K)
{
    constexpr int WGM = BM / WM, WGN = BN / WN, NW = WGM * WGN;
    constexpr int MI = WM / 16, NI = WN / 16;
    constexpr int SA_R = AROW ? BM : BK, SA_C = AROW ? BK : BM;
    constexpr int SB_R = BROW ? BK : BN, SB_C = BROW ? BN : BK;
    constexpr int CVA = SA_C / 8, CVB = SB_C / 8;
    constexpr int ITA = (SA_R * CVA) / (NW * 32);
    constexpr int ITB = (SB_R * CVB) / (NW * 32);
    static_assert((SA_R * CVA) % (NW * 32) == 0, "A copy div");
    static_assert((SB_R * CVB) % (NW * 32) == 0, "B copy div");

    __shared__ __nv_bfloat16 smA[SA_R][SA_C + 8];
    __shared__ __nv_bfloat16 smB[SB_R][SB_C + 8];
    __shared__ float stage[NW][16 * 16];
    __shared__ float aux[128];

    const int b = blockIdx.z;
    const __nv_bfloat16* Ab = A + strideA * (size_t)b;
    const __nv_bfloat16* Bb = Bm + strideB * (size_t)b;
    const size_t cb = strideC * (size_t)b;

    const int blockM = blockIdx.y * BM;
    const int blockN = blockIdx.x * BN;
    const int tid = threadIdx.x;
    const int wid = tid >> 5, lane = tid & 31;
    const int wm0 = (wid % WGM) * WM;
    const int wn0 = (wid / WGM) * WN;

    using ALayout = typename std::conditional<AROW, wmma::row_major, wmma::col_major>::type;
    using BLayout = typename std::conditional<BROW, wmma::row_major, wmma::col_major>::type;

    wmma::fragment<wmma::accumulator, 16, 16, 16, float> acc[MI][NI];
#pragma unroll
    for (int i = 0; i < MI; i++)
#pragma unroll
        for (int j = 0; j < NI; j++) wmma::fill_fragment(acc[i][j], 0.0f);

    // ---- stage tile 0 directly into smem ----
#pragma unroll
    for (int it = 0; it < ITA; ++it) {
        int idx = tid + it * NW * 32;
        int r = idx / CVA, cv = idx % CVA;
        const __nv_bfloat16* src = AROW
            ? Ab + (size_t)(blockM + r) * lda + cv * 8
            : Ab + (size_t)r * lda + blockM + cv * 8;
        *reinterpret_cast<uint4*>(&smA[r][cv * 8]) =
            *reinterpret_cast<const uint4*>(src);
    }
#pragma unroll
    for (int it = 0; it < ITB; ++it) {
        int idx = tid + it * NW * 32;
        int r = idx / CVB, cv = idx % CVB;
        const __nv_bfloat16* src = BROW
            ? Bb + (size_t)r * ldb + blockN + cv * 8
            : Bb + (size_t)(blockN + r) * ldb + cv * 8;
        *reinterpret_cast<uint4*>(&smB[r][cv * 8]) =
            *reinterpret_cast<const uint4*>(src);
    }
    __syncthreads();

    const int T = K / BK;
    for (int t = 0; t < T; ++t) {
        // ---- prefetch tile t+1 into registers (latency overlapped with MMA) ----
        uint4 pra[ITA], prb[ITB];
        if (t + 1 < T) {
            const int k0 = (t + 1) * BK;
#pragma unroll
            for (int it = 0; it < ITA; ++it) {
                int idx = tid + it * NW * 32;
                int r = idx / CVA, cv = idx % CVA;
                const __nv_bfloat16* src = AROW
                    ? Ab + (size_t)(blockM + r) * lda + k0 + cv * 8
                    : Ab + (size_t)(k0 + r) * lda + blockM + cv * 8;
                pra[it] = *reinterpret_cast<const uint4*>(src);
            }
#pragma unroll
            for (int it = 0; it < ITB; ++it) {
                int idx = tid + it * NW * 32;
                int r = idx / CVB, cv = idx % CVB;
                const __nv_bfloat16* src = BROW
                    ? Bb + (size_t)(k0 + r) * ldb + blockN + cv * 8
                    : Bb + (size_t)(blockN + r) * ldb + k0 + cv * 8;
                prb[it] = *reinterpret_cast<const uint4*>(src);
            }
        }

        // ---- MMA over smem tile t ----
#pragma unroll
        for (int kk = 0; kk < BK; kk += 16) {
            wmma::fragment<wmma::matrix_a, 16, 16, 16, __nv_bfloat16, ALayout> af[MI];
            wmma::fragment<wmma::matrix_b, 16, 16, 16, __nv_bfloat16, BLayout> bfr[NI];
#pragma unroll
            for (int i = 0; i < MI; i++) {
                const __nv_bfloat16* p = AROW ? &smA[wm0 + i * 16][kk]
                                              : &smA[kk][wm0 + i * 16];
                wmma::load_matrix_sync(af[i], p, SA_C + 8);
            }
#pragma unroll
            for (int j = 0; j < NI; j++) {
                const __nv_bfloat16* p = BROW ? &smB[kk][wn0 + j * 16]
                                              : &smB[wn0 + j * 16][kk];
                wmma::load_matrix_sync(bfr[j], p, SB_C + 8);
            }
#pragma unroll
            for (int i = 0; i < MI; i++)
#pragma unroll
                for (int j = 0; j < NI; j++)
                    wmma::mma_sync(acc[i][j], af[i], bfr[j], acc[i][j]);
        }
        __syncthreads();

        // ---- commit prefetched tile to smem ----
        if (t + 1 < T) {
#pragma unroll
            for (int it = 0; it < ITA; ++it) {
                int idx = tid + it * NW * 32;
                int r = idx / CVA, cv = idx % CVA;
                *reinterpret_cast<uint4*>(&smA[r][cv * 8]) = pra[it];
            }
#pragma unroll
            for (int it = 0; it < ITB; ++it) {
                int idx = tid + it * NW * 32;
                int r = idx / CVB, cv = idx % CVB;
                *reinterpret_cast<uint4*>(&smB[r][cv * 8]) = prb[it];
            }
            __syncthreads();
        }
    }

    // ---- epilogue via per-warp staging ----
    if (EPI == 2) {
        if (tid < BN) aux[tid] = gamma[0] / rowsum[(size_t)b * N + blockN + tid];
        __syncthreads();
    }

#pragma unroll
    for (int i = 0; i < MI; i++) {
#pragma unroll
        for (int j = 0; j < NI; j++) {
            wmma::store_matrix_sync(&stage[wid][0], acc[i][j], 16, wmma::mem_row_major);
            __syncwarp();
            int rowBase = blockM + wm0 + i * 16;
            int colBase = blockN + wn0 + j * 16;
#pragma unroll
            for (int e = lane; e < 256; e += 32) {
                int r = e >> 4, c = e & 15;
                float val = stage[wid][e];
                size_t o = (size_t)(rowBase + r) * ldc + colBase + c;
                if (EPI == 1) {
                    ((__nv_bfloat16*)Cm)[cb + o] = __float2bfloat16(val + bias[rowBase + r]);
                } else if (EPI == 4) {
                    ((__nv_bfloat16*)Cm)[cb + o] = __float2bfloat16(__expf(val));
                } else {  // EPI 2
                    ((float*)Cm)[cb + o] =
                        val * aux[wn0 + j * 16 + c] + xres[strideX * (size_t)b + o];
                }
            }
            __syncwarp();
        }
    }
}

// ---------------- launch ----------------
extern "C" void kernel_launch(void* const* d_in, const int* in_sizes, int n_in,
                              void* d_out, int out_size) {
    const float* x     = (const float*)d_in[0];
    const float* Wq    = (const float*)d_in[1];
    const float* bq    = (const float*)d_in[2];
    const float* Wk    = (const float*)d_in[3];
    const float* bk    = (const float*)d_in[4];
    const float* Wv    = (const float*)d_in[5];
    const float* bv    = (const float*)d_in[6];
    const float* gamma = (const float*)d_in[7];

    __nv_bfloat16 *xb, *wq, *wk, *wv, *q, *k, *v, *attn;
    float* rowsum;
    cudaGetSymbolAddress((void**)&xb, g_xb);
    cudaGetSymbolAddress((void**)&wq, g_Wq);
    cudaGetSymbolAddress((void**)&wk, g_Wk);
    cudaGetSymbolAddress((void**)&wv, g_Wv);
    cudaGetSymbolAddress((void**)&q, g_q);
    cudaGetSymbolAddress((void**)&k, g_k);
    cudaGetSymbolAddress((void**)&v, g_v);
    cudaGetSymbolAddress((void**)&attn, g_attn);
    cudaGetSymbolAddress((void**)&rowsum, g_rowsum);

    const size_t sX = (size_t)CCH * NPIX;   // per-batch x/v/out stride
    const size_t sQ = (size_t)CQD * NPIX;   // per-batch q/k stride
    const size_t sS = (size_t)NPIX * NPIX;  // per-batch attn stride

    // casts
    {
        size_t n4 = (size_t)BATCH * sX / 4;
        cast_kernel<<<(unsigned)((n4 + 255) / 256), 256>>>(x, xb, n4);
        size_t nq4 = (size_t)CQD * CCH / 4;
        cast_kernel<<<(unsigned)((nq4 + 255) / 256), 256>>>(Wq, wq, nq4);
        cast_kernel<<<(unsigned)((nq4 + 255) / 256), 256>>>(Wk, wk, nq4);
        size_t nv4 = (size_t)CCH * CCH / 4;
        cast_kernel<<<(unsigned)((nv4 + 255) / 256), 256>>>(Wv, wv, nv4);
    }

    // q = Wq @ xb + bq ; k = Wk @ xb + bk   [64 x 4096] per batch, bf16 out
    {
        dim3 g(NPIX / 128, CQD / 64, BATCH);
        gemm_bf16<64, 128, 64, 32, 32, true, true, 1><<<g, 256>>>(
            wq, 0, CCH, xb, sX, NPIX, q, sQ, NPIX, bq, nullptr, nullptr, 0,
            nullptr, CQD, NPIX, CCH);
        gemm_bf16<64, 128, 64, 32, 32, true, true, 1><<<g, 256>>>(
            wk, 0, CCH, xb, sX, NPIX, k, sQ, NPIX, bk, nullptr, nullptr, 0,
            nullptr, CQD, NPIX, CCH);
    }

    // v = Wv @ xb + bv   [512 x 4096] per batch, bf16 out
    {
        dim3 g(NPIX / 128, CCH / 128, BATCH);
        gemm_bf16<128, 128, 64, 64, 32, true, true, 1><<<g, 256>>>(
            wv, 0, CCH, xb, sX, NPIX, v, sX, NPIX, bv, nullptr, nullptr, 0,
            nullptr, CCH, NPIX, CCH);
    }

    // attn[i,j] = exp(sum_d q[d,i]*k[d,j])  bf16, unnormalized
    {
        dim3 g(NPIX / 128, NPIX / 128, BATCH);
        gemm_bf16<128, 128, 64, 64, 32, false, true, 4><<<g, 256>>>(
            q, sQ, NPIX, k, sQ, NPIX, attn, sS, NPIX, nullptr, nullptr,
            nullptr, 0, nullptr, NPIX, NPIX, CQD);
    }

    // rowsum[b,i] = sum_j attn[b,i,j]
    rowsum_kernel<<<BATCH * NPIX, 128>>>(attn, rowsum);

    // out[c,i] = gamma/rowsum[i] * sum_j v[c,j]*attn[i,j] + x[c,i]  -> fp32
    {
        dim3 g(NPIX / 128, CCH / 128, BATCH);
        gemm_bf16<128, 128, 64, 64, 32, true, false, 2><<<g, 256>>>(
            v, sX, NPIX, attn, sS, NPIX, d_out, sX, NPIX, nullptr, gamma,
            x, sX, rowsum, CCH, NPIX, NPIX);
    }
}

// round 11
// speedup vs baseline: 6.7708x; 1.3089x over previous

#include <cuda_runtime.h>
#include <cuda_bf16.h>
#include <mma.h>
#include <cstdint>
#include <cstddef>
#include <type_traits>

using namespace nvcuda;

#define BATCH 8
#define CCH   512
#define NPIX  4096
#define CQD   64

// ---------------- static scratch (no runtime allocation allowed) ----------------
__device__ __nv_bfloat16 g_xb[(size_t)BATCH * CCH * NPIX];     // x in bf16
__device__ __nv_bfloat16 g_Wq[CQD * CCH];
__device__ __nv_bfloat16 g_Wk[CQD * CCH];
__device__ __nv_bfloat16 g_Wv[CCH * CCH];
__device__ __nv_bfloat16 g_q[(size_t)BATCH * CQD * NPIX];
__device__ __nv_bfloat16 g_k[(size_t)BATCH * CQD * NPIX];
__device__ __nv_bfloat16 g_v[(size_t)BATCH * CCH * NPIX];
__device__ __nv_bfloat16 g_attn[(size_t)BATCH * NPIX * NPIX];  // exp(scores), unnormalized
__device__ float         g_rowsum[(size_t)BATCH * NPIX];

// ---------------- helpers ----------------
__device__ __forceinline__ uint32_t smem_u32(const void* p) {
    uint32_t a;
    asm("{ .reg .u64 t; cvta.to.shared.u64 t, %1; cvt.u32.u64 %0, t; }" : "=r"(a) : "l"(p));
    return a;
}
__device__ __forceinline__ void cpa16(uint32_t dst, const void* src) {
    asm volatile("cp.async.cg.shared.global [%0], [%1], 16;" :: "r"(dst), "l"(src));
}
#define CP_COMMIT() asm volatile("cp.async.commit_group;" ::: "memory")
#define CP_WAIT(n)  asm volatile("cp.async.wait_group %0;" :: "n"(n) : "memory")

// ---------------- fp32 -> bf16 cast (vectorized) ----------------
__global__ void cast_kernel(const float* __restrict__ in,
                            __nv_bfloat16* __restrict__ out, size_t n4) {
    size_t i = (size_t)blockIdx.x * blockDim.x + threadIdx.x;
    if (i < n4) {
        float4 f = reinterpret_cast<const float4*>(in)[i];
        __nv_bfloat162 a = __floats2bfloat162_rn(f.x, f.y);
        __nv_bfloat162 b = __floats2bfloat162_rn(f.z, f.w);
        uint2 u;
        u.x = *reinterpret_cast<unsigned*>(&a);
        u.y = *reinterpret_cast<unsigned*>(&b);
        reinterpret_cast<uint2*>(out)[i] = u;
    }
}

// ---------------- rowsum reduction over attn rows ----------------
__global__ void rowsum_kernel(const __nv_bfloat16* __restrict__ attn,
                              float* __restrict__ rowsum) {
    size_t row = blockIdx.x;
    const uint2* src = reinterpret_cast<const uint2*>(attn + row * NPIX);
    int t = threadIdx.x;
    float s = 0.0f;
#pragma unroll
    for (int i = 0; i < 8; ++i) {
        uint2 u = src[t + 128 * i];
        __nv_bfloat162 h0 = *reinterpret_cast<__nv_bfloat162*>(&u.x);
        __nv_bfloat162 h1 = *reinterpret_cast<__nv_bfloat162*>(&u.y);
        s += __bfloat162float(__low2bfloat16(h0)) + __bfloat162float(__high2bfloat16(h0));
        s += __bfloat162float(__low2bfloat16(h1)) + __bfloat162float(__high2bfloat16(h1));
    }
#pragma unroll
    for (int o = 16; o > 0; o >>= 1) s += __shfl_xor_sync(0xffffffffu, s, o);
    __shared__ float red[4];
    if ((t & 31) == 0) red[t >> 5] = s;
    __syncthreads();
    if (t == 0) rowsum[row] = red[0] + red[1] + red[2] + red[3];
}

// ============ pipelined 128x128 GEMM: cp.async 2-stage, 4 warps of 64x64 ============
// C[M,N] = A(MxK) * B(KxN), fp32 accumulate. 128 threads.
// EPI 1: bf16 (acc + bias[row]); EPI 2: fp32 (gamma/rowsum[col]*acc + xres); EPI 4: bf16 exp(acc)
template<bool AROW, bool BROW, int EPI>
__global__ void __launch_bounds__(128, 2)
gemm_pipe(const __nv_bfloat16* __restrict__ A, size_t strideA, int lda,
          const __nv_bfloat16* __restrict__ Bm, size_t strideB, int ldb,
          void* __restrict__ Cm, size_t strideC, int ldc,
          const float* __restrict__ bias,
          const float* __restrict__ gamma,
          const float* __restrict__ xres, size_t strideX,
          const float* __restrict__ rowsum,
          int M, int N, int K)
{
    constexpr int BM = 128, BN = 128, BK = 64, WM = 64, WN = 64;
    constexpr int WGM = BM / WM;                 // 2
    constexpr int MI = WM / 16, NI = WN / 16;    // 4, 4
    constexpr int SA_R = AROW ? BM : BK, SA_C = AROW ? BK : BM;
    constexpr int SB_R = BROW ? BK : BN, SB_C = BROW ? BN : BK;
    constexpr int LDA_S = SA_C + 8, LDB_S = SB_C + 8;
    constexpr int AELEM = SA_R * LDA_S;          // halves per A stage
    constexpr int BELEM = SB_R * LDB_S;
    constexpr int CVA = SA_C / 8, CVB = SB_C / 8;
    constexpr int ITA = (SA_R * CVA) / 128;      // 8
    constexpr int ITB = (SB_R * CVB) / 128;      // 8
    static_assert((SA_R * CVA) % 128 == 0 && (SB_R * CVB) % 128 == 0, "copy div");

    extern __shared__ char dsm[];
    __nv_bfloat16* smA = reinterpret_cast<__nv_bfloat16*>(dsm);
    __nv_bfloat16* smB = smA + 2 * AELEM;
    float* stage = reinterpret_cast<float*>(smB + 2 * BELEM);   // [4][256]
    float* aux = stage + 4 * 256;                               // [128]
    const uint32_t smA_u = smem_u32(smA);
    const uint32_t smB_u = smem_u32(smB);

    const int b = blockIdx.z;
    const __nv_bfloat16* Ab = A + strideA * (size_t)b;
    const __nv_bfloat16* Bb = Bm + strideB * (size_t)b;
    const size_t cb = strideC * (size_t)b;

    const int blockM = blockIdx.y * BM;
    const int blockN = blockIdx.x * BN;
    const int tid = threadIdx.x;
    const int wid = tid >> 5, lane = tid & 31;
    const int wm0 = (wid % WGM) * WM;
    const int wn0 = (wid / WGM) * WN;

    using ALayout = typename std::conditional<AROW, wmma::row_major, wmma::col_major>::type;
    using BLayout = typename std::conditional<BROW, wmma::row_major, wmma::col_major>::type;

    wmma::fragment<wmma::accumulator, 16, 16, 16, float> acc[MI][NI];
#pragma unroll
    for (int i = 0; i < MI; i++)
#pragma unroll
        for (int j = 0; j < NI; j++) wmma::fill_fragment(acc[i][j], 0.0f);

    // ---- prologue: cp.async stage 0 ----
#pragma unroll
    for (int it = 0; it < ITA; ++it) {
        int idx = tid + it * 128;
        int r = idx / CVA, cv = idx % CVA;
        const __nv_bfloat16* src = AROW
            ? Ab + (size_t)(blockM + r) * lda + cv * 8
            : Ab + (size_t)r * lda + blockM + cv * 8;
        cpa16(smA_u + (uint32_t)(r * LDA_S + cv * 8) * 2, src);
    }
#pragma unroll
    for (int it = 0; it < ITB; ++it) {
        int idx = tid + it * 128;
        int r = idx / CVB, cv = idx % CVB;
        const __nv_bfloat16* src = BROW
            ? Bb + (size_t)r * ldb + blockN + cv * 8
            : Bb + (size_t)(blockN + r) * ldb + cv * 8;
        cpa16(smB_u + (uint32_t)(r * LDB_S + cv * 8) * 2, src);
    }
    CP_COMMIT();

    const int T = K / BK;
    for (int t = 0; t < T; ++t) {
        const int cur = t & 1;
        if (t + 1 < T) {
            const int k0 = (t + 1) * BK;
            const uint32_t abuf = smA_u + (uint32_t)((cur ^ 1) * AELEM) * 2;
            const uint32_t bbuf = smB_u + (uint32_t)((cur ^ 1) * BELEM) * 2;
#pragma unroll
            for (int it = 0; it < ITA; ++it) {
                int idx = tid + it * 128;
                int r = idx / CVA, cv = idx % CVA;
                const __nv_bfloat16* src = AROW
                    ? Ab + (size_t)(blockM + r) * lda + k0 + cv * 8
                    : Ab + (size_t)(k0 + r) * lda + blockM + cv * 8;
                cpa16(abuf + (uint32_t)(r * LDA_S + cv * 8) * 2, src);
            }
#pragma unroll
            for (int it = 0; it < ITB; ++it) {
                int idx = tid + it * 128;
                int r = idx / CVB, cv = idx % CVB;
                const __nv_bfloat16* src = BROW
                    ? Bb + (size_t)(k0 + r) * ldb + blockN + cv * 8
                    : Bb + (size_t)(blockN + r) * ldb + k0 + cv * 8;
                cpa16(bbuf + (uint32_t)(r * LDB_S + cv * 8) * 2, src);
            }
            CP_COMMIT();
            CP_WAIT(1);
        } else {
            CP_WAIT(0);
        }
        __syncthreads();

        const __nv_bfloat16* a0 = smA + cur * AELEM;
        const __nv_bfloat16* b0 = smB + cur * BELEM;
#pragma unroll
        for (int kk = 0; kk < BK; kk += 16) {
            wmma::fragment<wmma::matrix_a, 16, 16, 16, __nv_bfloat16, ALayout> af[MI];
            wmma::fragment<wmma::matrix_b, 16, 16, 16, __nv_bfloat16, BLayout> bfr[NI];
#pragma unroll
            for (int i = 0; i < MI; i++) {
                const __nv_bfloat16* p = AROW ? a0 + (wm0 + i * 16) * LDA_S + kk
                                              : a0 + kk * LDA_S + wm0 + i * 16;
                wmma::load_matrix_sync(af[i], p, LDA_S);
            }
#pragma unroll
            for (int j = 0; j < NI; j++) {
                const __nv_bfloat16* p = BROW ? b0 + kk * LDB_S + wn0 + j * 16
                                              : b0 + (wn0 + j * 16) * LDB_S + kk;
                wmma::load_matrix_sync(bfr[j], p, LDB_S);
            }
#pragma unroll
            for (int i = 0; i < MI; i++)
#pragma unroll
                for (int j = 0; j < NI; j++)
                    wmma::mma_sync(acc[i][j], af[i], bfr[j], acc[i][j]);
        }
        __syncthreads();
    }

    // ---- epilogue via per-warp staging ----
    if (EPI == 2) {
        aux[tid] = gamma[0] / rowsum[(size_t)b * N + blockN + tid];
        __syncthreads();
    }

#pragma unroll
    for (int i = 0; i < MI; i++) {
#pragma unroll
        for (int j = 0; j < NI; j++) {
            wmma::store_matrix_sync(&stage[wid * 256], acc[i][j], 16, wmma::mem_row_major);
            __syncwarp();
            int rowBase = blockM + wm0 + i * 16;
            int colBase = blockN + wn0 + j * 16;
#pragma unroll
            for (int e = lane; e < 256; e += 32) {
                int r = e >> 4, c = e & 15;
                float val = stage[wid * 256 + e];
                size_t o = (size_t)(rowBase + r) * ldc + colBase + c;
                if (EPI == 1) {
                    ((__nv_bfloat16*)Cm)[cb + o] = __float2bfloat16(val + bias[rowBase + r]);
                } else if (EPI == 4) {
                    ((__nv_bfloat16*)Cm)[cb + o] = __float2bfloat16(__expf(val));
                } else {  // EPI 2
                    ((float*)Cm)[cb + o] =
                        val * aux[wn0 + j * 16 + c] + xres[strideX * (size_t)b + o];
                }
            }
            __syncwarp();
        }
    }
}

// host-side smem mirror for gemm_pipe
static constexpr size_t pipe_smem(bool AROW, bool BROW) {
    int SA_R = AROW ? 128 : 64, SA_C = AROW ? 64 : 128;
    int SB_R = BROW ? 64 : 128, SB_C = BROW ? 128 : 64;
    return (size_t)2 * (SA_R * (SA_C + 8) + SB_R * (SB_C + 8)) * 2 +
           (size_t)4 * 256 * 4 + 512;
}

// ---------- round-10 register-prefetch GEMM (kept for q/k projections) ----------
template<int BM, int BN, int BK, int WM, int WN, bool AROW, bool BROW, int EPI>
__global__ void __launch_bounds__((BM / WM) * (BN / WN) * 32)
gemm_bf16(const __nv_bfloat16* __restrict__ A, size_t strideA, int lda,
          const __nv_bfloat16* __restrict__ Bm, size_t strideB, int ldb,
          void* __restrict__ Cm, size_t strideC, int ldc,
          const float* __restrict__ bias,
          int M, int N, int K)
{
    constexpr int WGM = BM / WM, WGN = BN / WN, NW = WGM * WGN;
    constexpr int MI = WM / 16, NI = WN / 16;
    constexpr int SA_R = AROW ? BM : BK, SA_C = AROW ? BK : BM;
    constexpr int SB_R = BROW ? BK : BN, SB_C = BROW ? BN : BK;
    constexpr int CVA = SA_C / 8, CVB = SB_C / 8;
    constexpr int ITA = (SA_R * CVA) / (NW * 32);
    constexpr int ITB = (SB_R * CVB) / (NW * 32);

    __shared__ __nv_bfloat16 smA[SA_R][SA_C + 8];
    __shared__ __nv_bfloat16 smB[SB_R][SB_C + 8];
    __shared__ float stage[NW][16 * 16];

    const int b = blockIdx.z;
    const __nv_bfloat16* Ab = A + strideA * (size_t)b;
    const __nv_bfloat16* Bb = Bm + strideB * (size_t)b;
    const size_t cb = strideC * (size_t)b;

    const int blockM = blockIdx.y * BM;
    const int blockN = blockIdx.x * BN;
    const int tid = threadIdx.x;
    const int wid = tid >> 5, lane = tid & 31;
    const int wm0 = (wid % WGM) * WM;
    const int wn0 = (wid / WGM) * WN;

    using ALayout = typename std::conditional<AROW, wmma::row_major, wmma::col_major>::type;
    using BLayout = typename std::conditional<BROW, wmma::row_major, wmma::col_major>::type;

    wmma::fragment<wmma::accumulator, 16, 16, 16, float> acc[MI][NI];
#pragma unroll
    for (int i = 0; i < MI; i++)
#pragma unroll
        for (int j = 0; j < NI; j++) wmma::fill_fragment(acc[i][j], 0.0f);

#pragma unroll
    for (int it = 0; it < ITA; ++it) {
        int idx = tid + it * NW * 32;
        int r = idx / CVA, cv = idx % CVA;
        const __nv_bfloat16* src = AROW
            ? Ab + (size_t)(blockM + r) * lda + cv * 8
            : Ab + (size_t)r * lda + blockM + cv * 8;
        *reinterpret_cast<uint4*>(&smA[r][cv * 8]) = *reinterpret_cast<const uint4*>(src);
    }
#pragma unroll
    for (int it = 0; it < ITB; ++it) {
        int idx = tid + it * NW * 32;
        int r = idx / CVB, cv = idx % CVB;
        const __nv_bfloat16* src = BROW
            ? Bb + (size_t)r * ldb + blockN + cv * 8
            : Bb + (size_t)(blockN + r) * ldb + cv * 8;
        *reinterpret_cast<uint4*>(&smB[r][cv * 8]) = *reinterpret_cast<const uint4*>(src);
    }
    __syncthreads();

    const int T = K / BK;
    for (int t = 0; t < T; ++t) {
        uint4 pra[ITA], prb[ITB];
        if (t + 1 < T) {
            const int k0 = (t + 1) * BK;
#pragma unroll
            for (int it = 0; it < ITA; ++it) {
                int idx = tid + it * NW * 32;
                int r = idx / CVA, cv = idx % CVA;
                const __nv_bfloat16* src = AROW
                    ? Ab + (size_t)(blockM + r) * lda + k0 + cv * 8
                    : Ab + (size_t)(k0 + r) * lda + blockM + cv * 8;
                pra[it] = *reinterpret_cast<const uint4*>(src);
            }
#pragma unroll
            for (int it = 0; it < ITB; ++it) {
                int idx = tid + it * NW * 32;
                int r = idx / CVB, cv = idx % CVB;
                const __nv_bfloat16* src = BROW
                    ? Bb + (size_t)(k0 + r) * ldb + blockN + cv * 8
                    : Bb + (size_t)(blockN + r) * ldb + k0 + cv * 8;
                prb[it] = *reinterpret_cast<const uint4*>(src);
            }
        }

#pragma unroll
        for (int kk = 0; kk < BK; kk += 16) {
            wmma::fragment<wmma::matrix_a, 16, 16, 16, __nv_bfloat16, ALayout> af[MI];
            wmma::fragment<wmma::matrix_b, 16, 16, 16, __nv_bfloat16, BLayout> bfr[NI];
#pragma unroll
            for (int i = 0; i < MI; i++) {
                const __nv_bfloat16* p = AROW ? &smA[wm0 + i * 16][kk]
                                              : &smA[kk][wm0 + i * 16];
                wmma::load_matrix_sync(af[i], p, SA_C + 8);
            }
#pragma unroll
            for (int j = 0; j < NI; j++) {
                const __nv_bfloat16* p = BROW ? &smB[kk][wn0 + j * 16]
                                              : &smB[wn0 + j * 16][kk];
                wmma::load_matrix_sync(bfr[j], p, SB_C + 8);
            }
#pragma unroll
            for (int i = 0; i < MI; i++)
#pragma unroll
                for (int j = 0; j < NI; j++)
                    wmma::mma_sync(acc[i][j], af[i], bfr[j], acc[i][j]);
        }
        __syncthreads();

        if (t + 1 < T) {
#pragma unroll
            for (int it = 0; it < ITA; ++it) {
                int idx = tid + it * NW * 32;
                int r = idx / CVA, cv = idx % CVA;
                *reinterpret_cast<uint4*>(&smA[r][cv * 8]) = pra[it];
            }
#pragma unroll
            for (int it = 0; it < ITB; ++it) {
                int idx = tid + it * NW * 32;
                int r = idx / CVB, cv = idx % CVB;
                *reinterpret_cast<uint4*>(&smB[r][cv * 8]) = prb[it];
            }
            __syncthreads();
        }
    }

#pragma unroll
    for (int i = 0; i < MI; i++) {
#pragma unroll
        for (int j = 0; j < NI; j++) {
            wmma::store_matrix_sync(&stage[wid][0], acc[i][j], 16, wmma::mem_row_major);
            __syncwarp();
            int rowBase = blockM + wm0 + i * 16;
            int colBase = blockN + wn0 + j * 16;
#pragma unroll
            for (int e = lane; e < 256; e += 32) {
                int r = e >> 4, c = e & 15;
                float val = stage[wid][e];
                size_t o = (size_t)(rowBase + r) * ldc + colBase + c;
                ((__nv_bfloat16*)Cm)[cb + o] = __float2bfloat16(val + bias[rowBase + r]);
            }
            __syncwarp();
        }
    }
}

// ---------------- launch ----------------
extern "C" void kernel_launch(void* const* d_in, const int* in_sizes, int n_in,
                              void* d_out, int out_size) {
    const float* x     = (const float*)d_in[0];
    const float* Wq    = (const float*)d_in[1];
    const float* bq    = (const float*)d_in[2];
    const float* Wk    = (const float*)d_in[3];
    const float* bk    = (const float*)d_in[4];
    const float* Wv    = (const float*)d_in[5];
    const float* bv    = (const float*)d_in[6];
    const float* gamma = (const float*)d_in[7];

    __nv_bfloat16 *xb, *wq, *wk, *wv, *q, *k, *v, *attn;
    float* rowsum;
    cudaGetSymbolAddress((void**)&xb, g_xb);
    cudaGetSymbolAddress((void**)&wq, g_Wq);
    cudaGetSymbolAddress((void**)&wk, g_Wk);
    cudaGetSymbolAddress((void**)&wv, g_Wv);
    cudaGetSymbolAddress((void**)&q, g_q);
    cudaGetSymbolAddress((void**)&k, g_k);
    cudaGetSymbolAddress((void**)&v, g_v);
    cudaGetSymbolAddress((void**)&attn, g_attn);
    cudaGetSymbolAddress((void**)&rowsum, g_rowsum);

    const size_t sX = (size_t)CCH * NPIX;   // per-batch x/v/out stride
    const size_t sQ = (size_t)CQD * NPIX;   // per-batch q/k stride
    const size_t sS = (size_t)NPIX * NPIX;  // per-batch attn stride

    // casts
    {
        size_t n4 = (size_t)BATCH * sX / 4;
        cast_kernel<<<(unsigned)((n4 + 255) / 256), 256>>>(x, xb, n4);
        size_t nq4 = (size_t)CQD * CCH / 4;
        cast_kernel<<<(unsigned)((nq4 + 255) / 256), 256>>>(Wq, wq, nq4);
        cast_kernel<<<(unsigned)((nq4 + 255) / 256), 256>>>(Wk, wk, nq4);
        size_t nv4 = (size_t)CCH * CCH / 4;
        cast_kernel<<<(unsigned)((nv4 + 255) / 256), 256>>>(Wv, wv, nv4);
    }

    // q = Wq @ xb + bq ; k = Wk @ xb + bk   [64 x 4096] per batch, bf16 out
    {
        dim3 g(NPIX / 128, CQD / 64, BATCH);
        gemm_bf16<64, 128, 64, 32, 32, true, true, 1><<<g, 256>>>(
            wq, 0, CCH, xb, sX, NPIX, q, sQ, NPIX, bq, CQD, NPIX, CCH);
        gemm_bf16<64, 128, 64, 32, 32, true, true, 1><<<g, 256>>>(
            wk, 0, CCH, xb, sX, NPIX, k, sQ, NPIX, bk, CQD, NPIX, CCH);
    }

    // v = Wv @ xb + bv   [512 x 4096] per batch, bf16 out
    {
        auto kfn = gemm_pipe<true, true, 1>;
        size_t sm = pipe_smem(true, true);
        cudaFuncSetAttribute(kfn, cudaFuncAttributeMaxDynamicSharedMemorySize, (int)sm);
        dim3 g(NPIX / 128, CCH / 128, BATCH);
        kfn<<<g, 128, sm>>>(wv, 0, CCH, xb, sX, NPIX, v, sX, NPIX, bv,
                            nullptr, nullptr, 0, nullptr, CCH, NPIX, CCH);
    }

    // attn[i,j] = exp(sum_d q[d,i]*k[d,j])  bf16, unnormalized
    {
        auto kfn = gemm_pipe<false, true, 4>;
        size_t sm = pipe_smem(false, true);
        cudaFuncSetAttribute(kfn, cudaFuncAttributeMaxDynamicSharedMemorySize, (int)sm);
        dim3 g(NPIX / 128, NPIX / 128, BATCH);
        kfn<<<g, 128, sm>>>(q, sQ, NPIX, k, sQ, NPIX, attn, sS, NPIX, nullptr,
                            nullptr, nullptr, 0, nullptr, NPIX, NPIX, CQD);
    }

    // rowsum[b,i] = sum_j attn[b,i,j]
    rowsum_kernel<<<BATCH * NPIX, 128>>>(attn, rowsum);

    // out[c,i] = gamma/rowsum[i] * sum_j v[c,j]*attn[i,j] + x[c,i]  -> fp32
    {
        auto kfn = gemm_pipe<true, false, 2>;
        size_t sm = pipe_smem(true, false);
        cudaFuncSetAttribute(kfn, cudaFuncAttributeMaxDynamicSharedMemorySize, (int)sm);
        dim3 g(NPIX / 128, CCH / 128, BATCH);
        kfn<<<g, 128, sm>>>(v, sX, NPIX, attn, sS, NPIX, d_out, sX, NPIX, nullptr,
                            gamma, x, sX, rowsum, CCH, NPIX, NPIX);
    }
}